// round 11
// baseline (speedup 1.0000x reference)
#include <cuda_runtime.h>
#include <cuda_bf16.h>

// S=4096, H=3, E=512, G=3334, F=1, res=0.03
// out = sum_{s,h,e} mask*(b_h + w_h*feat)  -  0.03 * sum_{s,h,g} exp(b_h + w_h*grid)
//
// Row-aligned + row-halved (R6 structure), with the 3 h-rows of each pair
// INTERLEAVED in the grid loop: 3 independent load streams at the same k,
// unroll 2 -> 6 independent LDG.64 in flight per iteration within 32 regs.

#define S_DIM 4096
#define H_DIM 3
#define E_DIM 512
#define G_DIM 3334

constexpr int NBLK = 1024;
constexpr int NTHR = 256;

constexpr int EV_ROW4 = E_DIM / 4;            // 128 float4 per event row
constexpr int GR_ROW2 = G_DIM / 2;            // 1667 float2 per grid row
constexpr int GR_HALF_ITERS = 26;             // 26*32 = 832 float2 per half
constexpr int GR_SPLIT = 832;                 // half1 covers [832, 1667)

__device__ float g_part_log[NBLK];
__device__ float g_part_int[NBLK];
__device__ unsigned int g_done_count = 0;

__global__ void __launch_bounds__(NTHR, 8) lm_fused_kernel(
    const float* __restrict__ ev_feat,
    const int* __restrict__ ev_mask,      // bool -> int32 in the harness
    const float* __restrict__ gr_feat,
    const float* __restrict__ weights,
    const float* __restrict__ bases,
    const float* __restrict__ effects,
    float* __restrict__ out)
{
    const int lane = threadIdx.x & 31;
    const int wid  = threadIdx.x >> 5;
    const int warp = blockIdx.x * (NTHR / 32) + wid;   // 0..8191
    const int pair = warp >> 1;                        // 0..4095
    const int half = warp & 1;                         // 0 or 1

    constexpr float LOG2E = 1.4426950408889634f;
    const float wl0 = weights[0] * effects[0] * LOG2E;
    const float wl1 = weights[1] * effects[1] * LOG2E;
    const float wl2 = weights[2] * effects[2] * LOG2E;
    const float bl0 = bases[0] * LOG2E;
    const float bl1 = bases[1] * LOG2E;
    const float bl2 = bases[2] * LOG2E;

    float plog = 0.0f;
    float pint0 = 0.0f;
    float pint1 = 0.0f;

    // ---- Event part: rows 3*pair + h, this warp's half (64 float4 each) ----
    {
        const int kbase = half * (EV_ROW4 / 2) + lane;   // 0/64 + lane
        #pragma unroll
        for (int h = 0; h < 3; h++) {
            const int row = 3 * pair + h;
            const float4* __restrict__ f4 = (const float4*)ev_feat + (size_t)row * EV_ROW4;
            const int4*   __restrict__ m4 = (const int4*)ev_mask + (size_t)row * EV_ROW4;
            int   cnt = 0;
            float sum = 0.0f;
            #pragma unroll
            for (int i = 0; i < 2; i++) {
                const int k = kbase + 32 * i;
                const float4 f = f4[k];
                const int4   m = m4[k];
                if (m.x) { cnt++; sum += f.x; }
                if (m.y) { cnt++; sum += f.y; }
                if (m.z) { cnt++; sum += f.z; }
                if (m.w) { cnt++; sum += f.w; }
            }
            // b*cnt + w*sum, in exp2-domain constants * (1/log2e)... keep exact:
            // use original-domain b,w: recover from wl/bl by dividing is lossy;
            // instead accumulate cnt/sum per h in original domain:
            const float wv = (h == 0 ? wl0 : (h == 1 ? wl1 : wl2)) * 0.6931471805599453f;
            const float bv = (h == 0 ? bl0 : (h == 1 ? bl1 : bl2)) * 0.6931471805599453f;
            plog += fmaf(bv, (float)cnt, wv * sum);
        }
    }

    // ---- Grid part: 3 h-rows interleaved, this warp's half ----
    {
        const int kbase = half * GR_SPLIT + lane;
        const float2* __restrict__ gA = (const float2*)gr_feat + (size_t)(3 * pair + 0) * GR_ROW2;
        const float2* __restrict__ gB = (const float2*)gr_feat + (size_t)(3 * pair + 1) * GR_ROW2;
        const float2* __restrict__ gC = (const float2*)gr_feat + (size_t)(3 * pair + 2) * GR_ROW2;

        #pragma unroll 2
        for (int i = 0; i < GR_HALF_ITERS; i++) {
            const int k = kbase + 32 * i;
            const float2 va = gA[k];
            const float2 vb = gB[k];
            const float2 vc = gC[k];
            pint0 += exp2f(fmaf(wl0, va.x, bl0));
            pint1 += exp2f(fmaf(wl0, va.y, bl0));
            pint0 += exp2f(fmaf(wl1, vb.x, bl1));
            pint1 += exp2f(fmaf(wl1, vb.y, bl1));
            pint0 += exp2f(fmaf(wl2, vc.x, bl2));
            pint1 += exp2f(fmaf(wl2, vc.y, bl2));
        }
        if (half == 1 && lane < GR_ROW2 - 2 * GR_SPLIT) {   // tail floats 3328..3333 (3 float2/row)
            const int k = 2 * GR_SPLIT + lane;
            const float2 va = gA[k];
            const float2 vb = gB[k];
            const float2 vc = gC[k];
            pint0 += exp2f(fmaf(wl0, va.x, bl0));
            pint1 += exp2f(fmaf(wl0, va.y, bl0));
            pint0 += exp2f(fmaf(wl1, vb.x, bl1));
            pint1 += exp2f(fmaf(wl1, vb.y, bl1));
            pint0 += exp2f(fmaf(wl2, vc.x, bl2));
            pint1 += exp2f(fmaf(wl2, vc.y, bl2));
        }
    }

    float pint = pint0 + pint1;

    // ---- Block reduction ----
    __shared__ float s_log[NTHR / 32];
    __shared__ float s_int[NTHR / 32];
    __shared__ bool s_is_last;
    #pragma unroll
    for (int off = 16; off > 0; off >>= 1) {
        plog += __shfl_xor_sync(0xFFFFFFFFu, plog, off);
        pint += __shfl_xor_sync(0xFFFFFFFFu, pint, off);
    }
    if (lane == 0) { s_log[wid] = plog; s_int[wid] = pint; }
    __syncthreads();
    if (wid == 0) {
        float vl = (lane < NTHR / 32) ? s_log[lane] : 0.0f;
        float vi = (lane < NTHR / 32) ? s_int[lane] : 0.0f;
        #pragma unroll
        for (int off = 4; off > 0; off >>= 1) {
            vl += __shfl_xor_sync(0xFFFFFFFFu, vl, off);
            vi += __shfl_xor_sync(0xFFFFFFFFu, vi, off);
        }
        if (lane == 0) {
            g_part_log[blockIdx.x] = vl;
            g_part_int[blockIdx.x] = vi;
            __threadfence();
            unsigned int ticket = atomicAdd(&g_done_count, 1u);
            s_is_last = (ticket == (unsigned int)(NBLK - 1));
        }
    }
    __syncthreads();

    // ---- Last block: deterministic final combine in double ----
    if (s_is_last) {
        __shared__ double d_log[NTHR / 32];
        __shared__ double d_int[NTHR / 32];
        double dl = 0.0, di = 0.0;
        for (int j = threadIdx.x; j < NBLK; j += NTHR) {
            dl += (double)g_part_log[j];
            di += (double)g_part_int[j];
        }
        #pragma unroll
        for (int off = 16; off > 0; off >>= 1) {
            dl += __shfl_xor_sync(0xFFFFFFFFu, dl, off);
            di += __shfl_xor_sync(0xFFFFFFFFu, di, off);
        }
        if (lane == 0) { d_log[wid] = dl; d_int[wid] = di; }
        __syncthreads();
        if (threadIdx.x == 0) {
            double tl = 0.0, ti = 0.0;
            #pragma unroll
            for (int k = 0; k < NTHR / 32; k++) { tl += d_log[k]; ti += d_int[k]; }
            out[0] = (float)(tl - 0.03 * ti);
            g_done_count = 0;   // reset for next graph replay
        }
    }
}

extern "C" void kernel_launch(void* const* d_in, const int* in_sizes, int n_in,
                              void* d_out, int out_size)
{
    const float* ev_feat = (const float*)d_in[0];
    const int*   ev_mask = (const int*)d_in[1];
    const float* gr_feat = (const float*)d_in[2];
    const float* weights = (const float*)d_in[3];
    const float* bases   = (const float*)d_in[4];
    const float* effects = (const float*)d_in[5];
    float* out = (float*)d_out;

    lm_fused_kernel<<<NBLK, NTHR>>>(ev_feat, ev_mask, gr_feat, weights, bases, effects, out);
}

// round 12
// speedup vs baseline: 1.0207x; 1.0207x over previous
#include <cuda_runtime.h>
#include <cuda_bf16.h>

// S=4096, H=3, E=512, G=3334, F=1, res=0.03
// out = sum_{s,h,e} mask*(b_h + w_h*feat)  -  0.03 * sum_{s,h,g} exp(b_h + w_h*grid)
//
// Oversubscribed small blocks for CLC work-stealing:
//   4096 blocks, block b owns sample-pair p=b -> rows 3p+0/1/2 (contiguous).
//   Warps 0..5: event part (row h=wi>>1, half=wi&1, 64 float4 each) [R6 scheme].
//   Warps 0..7: grid part, per row h (literal) strip k in [208*wi, 208*wi+208)
//   float2 (6 full warp-iters + 1 half iter); warp 7 lanes 0..2 take the
//   3-float2 row tail. All loads __ldcs (read-once streaming).

#define S_DIM 4096
#define H_DIM 3
#define E_DIM 512
#define G_DIM 3334

constexpr int NBLK = 4096;
constexpr int NTHR = 256;

constexpr int EV_ROW4 = E_DIM / 4;            // 128 float4 per event row
constexpr int GR_ROW2 = G_DIM / 2;            // 1667 float2 per grid row
constexpr int STRIP  = 208;                   // 8*208 = 1664; +3 tail = 1667

__device__ float g_part_log[NBLK];
__device__ float g_part_int[NBLK];
__device__ unsigned int g_done_count = 0;

__global__ void __launch_bounds__(NTHR, 8) lm_fused_kernel(
    const float* __restrict__ ev_feat,
    const int* __restrict__ ev_mask,      // bool -> int32 in the harness
    const float* __restrict__ gr_feat,
    const float* __restrict__ weights,
    const float* __restrict__ bases,
    const float* __restrict__ effects,
    float* __restrict__ out)
{
    const int lane = threadIdx.x & 31;
    const int wi   = threadIdx.x >> 5;     // warp in block, 0..7
    const int pair = blockIdx.x;           // 0..4095

    constexpr float LOG2E = 1.4426950408889634f;
    float wv[3], bv[3], wl[3], bl[3];
    #pragma unroll
    for (int h = 0; h < 3; h++) {
        wv[h] = weights[h] * effects[h];
        bv[h] = bases[h];
        wl[h] = wv[h] * LOG2E;
        bl[h] = bv[h] * LOG2E;
    }

    float plog = 0.0f;
    float pint0 = 0.0f;
    float pint1 = 0.0f;

    // ---- Event part: warps 0..5, row h = wi>>1, half = wi&1 (64 float4) ----
    if (wi < 6) {
        const int h    = wi >> 1;
        const int half = wi & 1;
        const int row  = 3 * pair + h;
        const float4* __restrict__ f4 = (const float4*)ev_feat + (size_t)row * EV_ROW4;
        const int4*   __restrict__ m4 = (const int4*)ev_mask + (size_t)row * EV_ROW4;
        const int kbase = half * (EV_ROW4 / 2) + lane;
        int   cnt = 0;
        float sum = 0.0f;
        #pragma unroll
        for (int i = 0; i < 2; i++) {
            const int k = kbase + 32 * i;
            const float4 f = __ldcs(f4 + k);
            const int4   m = __ldcs(m4 + k);
            if (m.x) { cnt++; sum += f.x; }
            if (m.y) { cnt++; sum += f.y; }
            if (m.z) { cnt++; sum += f.z; }
            if (m.w) { cnt++; sum += f.w; }
        }
        const float wh = (h == 0) ? wv[0] : ((h == 1) ? wv[1] : wv[2]);
        const float bh = (h == 0) ? bv[0] : ((h == 1) ? bv[1] : bv[2]);
        plog = fmaf(bh, (float)cnt, wh * sum);
    }

    // ---- Grid part: all 8 warps; per-row strip [208*wi, 208*wi+208) ----
    {
        const int kbase = STRIP * wi + lane;
        #pragma unroll
        for (int h = 0; h < 3; h++) {
            const int row = 3 * pair + h;
            const float2* __restrict__ g2 = (const float2*)gr_feat + (size_t)row * GR_ROW2;
            const float ww = wl[h];
            const float bb = bl[h];
            #pragma unroll 3
            for (int i = 0; i < 6; i++) {
                const float2 g = __ldcs(g2 + kbase + 32 * i);
                pint0 += exp2f(fmaf(ww, g.x, bb));
                pint1 += exp2f(fmaf(ww, g.y, bb));
            }
            if (lane < 16) {                         // half iter: 192..207 of strip
                const float2 g = __ldcs(g2 + kbase + 192);
                pint0 += exp2f(fmaf(ww, g.x, bb));
                pint1 += exp2f(fmaf(ww, g.y, bb));
            }
            if (wi == 7 && lane < GR_ROW2 - 8 * STRIP) {   // row tail: k = 1664..1666
                const float2 g = __ldcs(g2 + 8 * STRIP + lane);
                pint0 += exp2f(fmaf(ww, g.x, bb));
                pint1 += exp2f(fmaf(ww, g.y, bb));
            }
        }
    }

    float pint = pint0 + pint1;

    // ---- Block reduction ----
    __shared__ float s_log[NTHR / 32];
    __shared__ float s_int[NTHR / 32];
    __shared__ bool s_is_last;
    #pragma unroll
    for (int off = 16; off > 0; off >>= 1) {
        plog += __shfl_xor_sync(0xFFFFFFFFu, plog, off);
        pint += __shfl_xor_sync(0xFFFFFFFFu, pint, off);
    }
    if (lane == 0) { s_log[wi] = plog; s_int[wi] = pint; }
    __syncthreads();
    if (wi == 0) {
        float vl = (lane < NTHR / 32) ? s_log[lane] : 0.0f;
        float vi = (lane < NTHR / 32) ? s_int[lane] : 0.0f;
        #pragma unroll
        for (int off = 4; off > 0; off >>= 1) {
            vl += __shfl_xor_sync(0xFFFFFFFFu, vl, off);
            vi += __shfl_xor_sync(0xFFFFFFFFu, vi, off);
        }
        if (lane == 0) {
            g_part_log[blockIdx.x] = vl;
            g_part_int[blockIdx.x] = vi;
            __threadfence();
            unsigned int ticket = atomicAdd(&g_done_count, 1u);
            s_is_last = (ticket == (unsigned int)(NBLK - 1));
        }
    }
    __syncthreads();

    // ---- Last block: deterministic final combine in double ----
    if (s_is_last) {
        __shared__ double d_log[NTHR / 32];
        __shared__ double d_int[NTHR / 32];
        double dl = 0.0, di = 0.0;
        for (int j = threadIdx.x; j < NBLK; j += NTHR) {
            dl += (double)g_part_log[j];
            di += (double)g_part_int[j];
        }
        #pragma unroll
        for (int off = 16; off > 0; off >>= 1) {
            dl += __shfl_xor_sync(0xFFFFFFFFu, dl, off);
            di += __shfl_xor_sync(0xFFFFFFFFu, di, off);
        }
        if (lane == 0) { d_log[wi] = dl; d_int[wi] = di; }
        __syncthreads();
        if (threadIdx.x == 0) {
            double tl = 0.0, ti = 0.0;
            #pragma unroll
            for (int k = 0; k < NTHR / 32; k++) { tl += d_log[k]; ti += d_int[k]; }
            out[0] = (float)(tl - 0.03 * ti);
            g_done_count = 0;   // reset for next graph replay
        }
    }
}

extern "C" void kernel_launch(void* const* d_in, const int* in_sizes, int n_in,
                              void* d_out, int out_size)
{
    const float* ev_feat = (const float*)d_in[0];
    const int*   ev_mask = (const int*)d_in[1];
    const float* gr_feat = (const float*)d_in[2];
    const float* weights = (const float*)d_in[3];
    const float* bases   = (const float*)d_in[4];
    const float* effects = (const float*)d_in[5];
    float* out = (float*)d_out;

    lm_fused_kernel<<<NBLK, NTHR>>>(ev_feat, ev_mask, gr_feat, weights, bases, effects, out);
}

// round 16
// speedup vs baseline: 1.2873x; 1.2612x over previous
#include <cuda_runtime.h>
#include <cuda_bf16.h>
#include <cstdint>

// S=4096, H=3, E=512, G=3334, F=1, res=0.03
// out = sum_{s,h,e} mask*(b_h + w_h*feat)  -  0.03 * sum_{s,h,g} exp(b_h + w_h*grid)
//
// R6 pair/half partition (8192 warps; warp w -> pair p=w>>1 rows 3p+0/1/2,
// half=w&1), with the grid loads moved to a per-warp cp.async (LDGSTS) ring:
// 8 buffers x 256B per warp, depth-7 pipeline -> in-flight bytes no longer
// limited by the 32-register budget. Addresses are identical to R6.

#define S_DIM 4096
#define H_DIM 3
#define E_DIM 512
#define G_DIM 3334

constexpr int NBLK = 1024;
constexpr int NTHR = 256;
constexpr int NW   = NTHR / 32;               // 8 warps/block

constexpr int EV_ROW4 = E_DIM / 4;            // 128 float4 per event row
constexpr int GR_ROW2 = G_DIM / 2;            // 1667 float2 per grid row
constexpr int GR_SPLIT = 832;                 // half1 covers [832, 1667)
constexpr int ITERS_PER_ROW = 26;             // 26*32 = 832 float2 per half-row
constexpr int NSTAGE = 3 * ITERS_PER_ROW;     // 78 virtual stages per warp

__device__ float g_part_log[NBLK];
__device__ float g_part_int[NBLK];
__device__ unsigned int g_done_count = 0;

__device__ __forceinline__ void cp_async8(unsigned int dst_smem, const void* src) {
    asm volatile("cp.async.ca.shared.global [%0], [%1], 8;\n" :: "r"(dst_smem), "l"(src));
}
__device__ __forceinline__ void cp_commit() {
    asm volatile("cp.async.commit_group;\n");
}
#define CP_WAIT(n) asm volatile("cp.async.wait_group %0;\n" :: "n"(n))

__global__ void __launch_bounds__(NTHR, 8) lm_fused_kernel(
    const float* __restrict__ ev_feat,
    const int* __restrict__ ev_mask,      // bool -> int32 in the harness
    const float* __restrict__ gr_feat,
    const float* __restrict__ weights,
    const float* __restrict__ bases,
    const float* __restrict__ effects,
    float* __restrict__ out)
{
    const int lane = threadIdx.x & 31;
    const int wi   = threadIdx.x >> 5;
    const int warp = blockIdx.x * NW + wi;             // 0..8191
    const int pair = warp >> 1;                        // 0..4095
    const int half = warp & 1;                         // 0 or 1

    constexpr float LOG2E = 1.4426950408889634f;
    const float wv0 = weights[0] * effects[0];
    const float wv1 = weights[1] * effects[1];
    const float wv2 = weights[2] * effects[2];
    const float bv0 = bases[0], bv1 = bases[1], bv2 = bases[2];
    const float wl0 = wv0 * LOG2E, wl1 = wv1 * LOG2E, wl2 = wv2 * LOG2E;
    const float bl0 = bv0 * LOG2E, bl1 = bv1 * LOG2E, bl2 = bv2 * LOG2E;

    float plog = 0.0f;
    float pint0 = 0.0f;
    float pint1 = 0.0f;

    // ---- Event part: rows 3*pair + h, this warp's half (64 float4 each) ----
    {
        const int kbase = half * (EV_ROW4 / 2) + lane;   // 0/64 + lane
        #pragma unroll
        for (int h = 0; h < 3; h++) {
            const int row = 3 * pair + h;
            const float4* __restrict__ f4 = (const float4*)ev_feat + (size_t)row * EV_ROW4;
            const int4*   __restrict__ m4 = (const int4*)ev_mask + (size_t)row * EV_ROW4;
            int   cnt = 0;
            float sum = 0.0f;
            #pragma unroll
            for (int i = 0; i < 2; i++) {
                const int k = kbase + 32 * i;
                const float4 f = f4[k];
                const int4   m = m4[k];
                if (m.x) { cnt++; sum += f.x; }
                if (m.y) { cnt++; sum += f.y; }
                if (m.z) { cnt++; sum += f.z; }
                if (m.w) { cnt++; sum += f.w; }
            }
            const float wh = (h == 0) ? wv0 : ((h == 1) ? wv1 : wv2);
            const float bh = (h == 0) ? bv0 : ((h == 1) ? bv1 : bv2);
            plog += fmaf(bh, (float)cnt, wh * sum);
        }
    }

    // ---- Grid part: cp.async ring, addresses identical to R6 ----
    {
        __shared__ __align__(16) float2 ring[NW][8][32];   // 16 KB/block
        const unsigned int dst0 = (unsigned int)__cvta_generic_to_shared(&ring[wi][0][lane]);

        const int kbase = half * GR_SPLIT + lane;
        const float2* __restrict__ gA = (const float2*)gr_feat + (size_t)(3 * pair + 0) * GR_ROW2 + kbase;
        const float2* __restrict__ gB = (const float2*)gr_feat + (size_t)(3 * pair + 1) * GR_ROW2 + kbase;
        const float2* __restrict__ gC = (const float2*)gr_feat + (size_t)(3 * pair + 2) * GR_ROW2 + kbase;

        // issue stage s (0..77): row = s/26 (by compare), i = s - 26*row
        auto issue = [&](int s) {
            const float2* src;
            int i;
            if (s < ITERS_PER_ROW)          { src = gA; i = s; }
            else if (s < 2 * ITERS_PER_ROW) { src = gB; i = s - ITERS_PER_ROW; }
            else                            { src = gC; i = s - 2 * ITERS_PER_ROW; }
            cp_async8(dst0 + (unsigned int)(s & 7) * 256u, (const void*)(src + 32 * i));
            cp_commit();
        };
        auto compute = [&](int c) {
            const float2 v = ring[wi][c & 7][lane];
            float ww, bb;
            if (c < ITERS_PER_ROW)          { ww = wl0; bb = bl0; }
            else if (c < 2 * ITERS_PER_ROW) { ww = wl1; bb = bl1; }
            else                            { ww = wl2; bb = bl2; }
            pint0 += exp2f(fmaf(ww, v.x, bb));
            pint1 += exp2f(fmaf(ww, v.y, bb));
        };

        #pragma unroll
        for (int s = 0; s < 7; s++) issue(s);            // prologue
        #pragma unroll 2
        for (int s = 7; s < NSTAGE; s++) {               // main: issue s, compute s-7
            issue(s);
            CP_WAIT(6);
            compute(s - 7);
        }
        CP_WAIT(0);                                      // epilogue
        #pragma unroll
        for (int c = NSTAGE - 7; c < NSTAGE; c++) compute(c);

        // row tail: float2 k = 1664..1666 (3 per row), half1 lanes 0..2
        if (half == 1 && lane < GR_ROW2 - 2 * GR_SPLIT) {
            const int k = 2 * GR_SPLIT + lane - kbase;   // offset from gX base
            const float2 va = gA[k];
            const float2 vb = gB[k];
            const float2 vc = gC[k];
            pint0 += exp2f(fmaf(wl0, va.x, bl0));
            pint1 += exp2f(fmaf(wl0, va.y, bl0));
            pint0 += exp2f(fmaf(wl1, vb.x, bl1));
            pint1 += exp2f(fmaf(wl1, vb.y, bl1));
            pint0 += exp2f(fmaf(wl2, vc.x, bl2));
            pint1 += exp2f(fmaf(wl2, vc.y, bl2));
        }
    }

    float pint = pint0 + pint1;

    // ---- Block reduction ----
    __shared__ float s_log[NW];
    __shared__ float s_int[NW];
    __shared__ bool s_is_last;
    #pragma unroll
    for (int off = 16; off > 0; off >>= 1) {
        plog += __shfl_xor_sync(0xFFFFFFFFu, plog, off);
        pint += __shfl_xor_sync(0xFFFFFFFFu, pint, off);
    }
    if (lane == 0) { s_log[wi] = plog; s_int[wi] = pint; }
    __syncthreads();
    if (wi == 0) {
        float vl = (lane < NW) ? s_log[lane] : 0.0f;
        float vi = (lane < NW) ? s_int[lane] : 0.0f;
        #pragma unroll
        for (int off = 4; off > 0; off >>= 1) {
            vl += __shfl_xor_sync(0xFFFFFFFFu, vl, off);
            vi += __shfl_xor_sync(0xFFFFFFFFu, vi, off);
        }
        if (lane == 0) {
            g_part_log[blockIdx.x] = vl;
            g_part_int[blockIdx.x] = vi;
            __threadfence();
            unsigned int ticket = atomicAdd(&g_done_count, 1u);
            s_is_last = (ticket == (unsigned int)(NBLK - 1));
        }
    }
    __syncthreads();

    // ---- Last block: deterministic final combine in double ----
    if (s_is_last) {
        __shared__ double d_log[NW];
        __shared__ double d_int[NW];
        double dl = 0.0, di = 0.0;
        for (int j = threadIdx.x; j < NBLK; j += NTHR) {
            dl += (double)g_part_log[j];
            di += (double)g_part_int[j];
        }
        #pragma unroll
        for (int off = 16; off > 0; off >>= 1) {
            dl += __shfl_xor_sync(0xFFFFFFFFu, dl, off);
            di += __shfl_xor_sync(0xFFFFFFFFu, di, off);
        }
        if (lane == 0) { d_log[wi] = dl; d_int[wi] = di; }
        __syncthreads();
        if (threadIdx.x == 0) {
            double tl = 0.0, ti = 0.0;
            #pragma unroll
            for (int k = 0; k < NW; k++) { tl += d_log[k]; ti += d_int[k]; }
            out[0] = (float)(tl - 0.03 * ti);
            g_done_count = 0;   // reset for next graph replay
        }
    }
}

extern "C" void kernel_launch(void* const* d_in, const int* in_sizes, int n_in,
                              void* d_out, int out_size)
{
    const float* ev_feat = (const float*)d_in[0];
    const int*   ev_mask = (const int*)d_in[1];
    const float* gr_feat = (const float*)d_in[2];
    const float* weights = (const float*)d_in[3];
    const float* bases   = (const float*)d_in[4];
    const float* effects = (const float*)d_in[5];
    float* out = (float*)d_out;

    lm_fused_kernel<<<NBLK, NTHR>>>(ev_feat, ev_mask, gr_feat, weights, bases, effects, out);
}